// round 1
// baseline (speedup 1.0000x reference)
#include <cuda_runtime.h>

// LSTM: B=512, T=1000, IN=39, H=64 (4H=256 gates), OUT=48.
// Persistent kernel: 128 CTAs x 256 threads, 4 batch rows per CTA.
// Batch rows are independent -> no inter-CTA sync. Weights live in
// registers (gate weights) / SMEM (output head). All math fp32 via
// Blackwell packed fma.rn.f32x2 (2 MACs per instruction).

#define B_    512
#define T_    1000
#define IN_   39
#define H_    64
#define G_    256   // 4*H
#define OUT_  48
#define ROWS  4
#define CTAS  (B_/ROWS)   // 128
#define NTHR  256

typedef unsigned long long u64;

__device__ __forceinline__ u64 fma2(u64 a, u64 b, u64 c) {
    u64 d;
    asm("fma.rn.f32x2 %0, %1, %2, %3;" : "=l"(d) : "l"(a), "l"(b), "l"(c));
    return d;
}
__device__ __forceinline__ u64 pack2(float lo, float hi) {
    u64 d;
    asm("mov.b64 %0, {%1, %2};" : "=l"(d) : "f"(lo), "f"(hi));
    return d;
}
__device__ __forceinline__ void unpack2(u64 v, float &lo, float &hi) {
    asm("mov.b64 {%0, %1}, %2;" : "=f"(lo), "=f"(hi) : "l"(v));
}
// Accurate-enough fp32 activations (expf ~2 ulp); saturate correctly at +-inf.
__device__ __forceinline__ float sigm(float x) {
    return __fdividef(1.0f, 1.0f + __expf(-x));
}
__device__ __forceinline__ float tanh_(float x) {
    float e = __expf(2.0f * x);            // 0 .. inf
    return 1.0f - __fdividef(2.0f, e + 1.0f); // -1 .. 1, no inf/inf
}

__global__ void __launch_bounds__(NTHR, 1)
lstm_persist_kernel(const float* __restrict__ x,
                    const float* __restrict__ W_ih,
                    const float* __restrict__ W_hh,
                    const float* __restrict__ b_ih,
                    const float* __restrict__ b_hh,
                    const float* __restrict__ W_out,
                    const float* __restrict__ b_out,
                    float* __restrict__ out)
{
    __shared__ __align__(16) float xs[2][ROWS][40];   // x slice, double-buffered, padded 39->40
    __shared__ __align__(16) float hs[ROWS][H_];      // hidden state
    __shared__ __align__(16) float gbuf[ROWS][G_];    // gate preactivations
    __shared__ __align__(16) u64   woutS[H_/2][OUT_]; // W_out as f32x2 pairs, [k-pair][o]
    __shared__ float boutS[OUT_];

    const int tid  = threadIdx.x;
    const int row0 = blockIdx.x * ROWS;

    // ---- per-thread gate weights in registers: [W_ih row | W_hh row] as 52 pairs ----
    u64 wv[52];
    {
        const int g = tid;  // gate index 0..255
        #pragma unroll
        for (int k2 = 0; k2 < 20; k2++) {
            float lo = (2*k2     < IN_) ? W_ih[g*IN_ + 2*k2    ] : 0.0f;
            float hi = (2*k2 + 1 < IN_) ? W_ih[g*IN_ + 2*k2 + 1] : 0.0f;
            wv[k2] = pack2(lo, hi);
        }
        #pragma unroll
        for (int k2 = 0; k2 < 32; k2++) {
            wv[20 + k2] = pack2(W_hh[g*H_ + 2*k2], W_hh[g*H_ + 2*k2 + 1]);
        }
    }
    const u64 bias2 = pack2(b_ih[tid] + b_hh[tid], 0.0f);

    // ---- stage output head (W_out pairs, transposed) + b_out in SMEM ----
    for (int idx = tid; idx < (H_/2)*OUT_; idx += NTHR) {
        int k2 = idx / OUT_, o = idx % OUT_;
        woutS[k2][o] = pack2(W_out[o*H_ + 2*k2], W_out[o*H_ + 2*k2 + 1]);
    }
    if (tid < OUT_) boutS[tid] = b_out[tid];

    // ---- zero h state and x buffers (incl. pad element) ----
    hs[tid >> 6][tid & 63] = 0.0f;
    for (int idx = tid; idx < 2*ROWS*40; idx += NTHR)
        ((float*)xs)[idx] = 0.0f;
    __syncthreads();

    // ---- t=0 x slice ----
    if (tid < ROWS*IN_) {
        int r = tid / IN_, i = tid % IN_;
        xs[0][r][i] = x[((size_t)(row0 + r) * T_) * IN_ + i];
    }

    // ---- per-thread output-head constants ----
    int orow = 0, ocol = 0;
    u64 bo2 = pack2(0.0f, 0.0f);
    if (tid < ROWS*OUT_) {
        orow = tid / OUT_;
        ocol = tid - orow*OUT_;
        bo2  = pack2(b_out[ocol], 0.0f);
    }

    const int ur = tid >> 6;   // row for cell-state update
    const int uu = tid & 63;   // hidden unit
    float creg = 0.0f;         // cell state, lives in a register

    // prefetch mapping (valid when tid < ROWS*IN_)
    const int pr = (tid < ROWS*IN_) ? (tid / IN_) : 0;
    const int pi = (tid < ROWS*IN_) ? (tid % IN_) : 0;

    __syncthreads();

    for (int t = 0; t < T_; t++) {
        const int p = t & 1;

        // prefetch next timestep's x into a register (latency hidden by Phase A)
        float xv = 0.0f;
        const bool pf = (tid < ROWS*IN_) && (t + 1 < T_);
        if (pf) xv = x[((size_t)(row0 + pr) * T_ + (t + 1)) * IN_ + pi];

        // ---- Phase A: gate preactivations. thread g computes gate g for all 4 rows ----
        #pragma unroll
        for (int r = 0; r < ROWS; r++) {
            u64 acc = bias2;
            const ulonglong2* xp = (const ulonglong2*)xs[p][r];  // 10 x 16B
            #pragma unroll
            for (int k = 0; k < 10; k++) {
                ulonglong2 q = xp[k];
                acc = fma2(wv[2*k    ], q.x, acc);
                acc = fma2(wv[2*k + 1], q.y, acc);
            }
            const ulonglong2* hp = (const ulonglong2*)hs[r];     // 16 x 16B
            #pragma unroll
            for (int k = 0; k < 16; k++) {
                ulonglong2 q = hp[k];
                acc = fma2(wv[20 + 2*k], q.x, acc);
                acc = fma2(wv[21 + 2*k], q.y, acc);
            }
            float lo, hi; unpack2(acc, lo, hi);
            gbuf[r][tid] = lo + hi;
        }
        __syncthreads();

        // ---- Phase B: activations + cell/hidden update. thread -> (row, hidden unit) ----
        {
            float gi = gbuf[ur][uu      ];
            float gf = gbuf[ur][uu +  64];
            float gg = gbuf[ur][uu + 128];
            float go = gbuf[ur][uu + 192];
            float iv = sigm(gi), fv = sigm(gf);
            float gv = tanh_(gg), ov = sigm(go);
            creg = fv * creg + iv * gv;
            hs[ur][uu] = ov * tanh_(creg);
        }
        if (pf) xs[p ^ 1][pr][pi] = xv;  // publish prefetched x for next step
        __syncthreads();

        // ---- Phase C: output head y = sigmoid(h @ W_out^T + b_out) ----
        if (tid < ROWS*OUT_) {
            u64 acc = bo2;
            const ulonglong2* hp = (const ulonglong2*)hs[orow];
            #pragma unroll
            for (int k = 0; k < 16; k++) {
                ulonglong2 q = hp[k];
                acc = fma2(woutS[2*k    ][ocol], q.x, acc);
                acc = fma2(woutS[2*k + 1][ocol], q.y, acc);
            }
            float lo, hi; unpack2(acc, lo, hi);
            out[((size_t)(row0 + orow) * T_ + t) * OUT_ + ocol] = sigm(lo + hi);
        }
        // No extra sync needed: Phase C only reads hs/woutS; next Phase A only
        // reads hs/xs and writes gbuf (whose last readers finished before the
        // sync above). hs is next written in Phase B, after the next sync.
    }
}

extern "C" void kernel_launch(void* const* d_in, const int* in_sizes, int n_in,
                              void* d_out, int out_size)
{
    (void)in_sizes; (void)n_in; (void)out_size;
    const float* x     = (const float*)d_in[0];
    const float* W_ih  = (const float*)d_in[1];
    const float* W_hh  = (const float*)d_in[2];
    const float* b_ih  = (const float*)d_in[3];
    const float* b_hh  = (const float*)d_in[4];
    const float* W_out = (const float*)d_in[5];
    const float* b_out = (const float*)d_in[6];
    float* out = (float*)d_out;

    lstm_persist_kernel<<<CTAS, NTHR>>>(x, W_ih, W_hh, b_ih, b_hh, W_out, b_out, out);
}